// round 7
// baseline (speedup 1.0000x reference)
#include <cuda_runtime.h>
#include <cuda_fp16.h>
#include <cstdint>
#include <math.h>

// ---------------------------------------------------------------------------
// Problem constants
// ---------------------------------------------------------------------------
#define BATCH 4
#define SEQ   2048
#define FDIM  1024
#define DKDIM 1024

// ---------------------------------------------------------------------------
// fp16 mma.sync GEMM tiling: CTA 128x256, warp 64x64, BK=64, 3 stages
// ---------------------------------------------------------------------------
#define BM 128
#define BN 256
#define BK 64
#define STAGES 3
#define GEMM_THREADS 256

#define ROWH 72                                  // padded row length in halves (BK + 8)
#define A_STAGE_HALVES (BM * ROWH)               // 9216
#define B_STAGE_HALVES (BN * ROWH)               // 18432
#define STAGE_HALVES   (A_STAGE_HALVES + B_STAGE_HALVES)
#define GEMM_SMEM      (STAGES * STAGE_HALVES * 2)   // 165,888 B

// ---------------------------------------------------------------------------
// Scratch (device globals — no dynamic allocation allowed)
// ---------------------------------------------------------------------------
__device__ __half g_xh  [(size_t)BATCH * SEQ * FDIM];
__device__ __half g_qkv [(size_t)BATCH * SEQ * 3 * DKDIM];   // Q|K|V interleaved in N
__device__ __half g_vt  [(size_t)BATCH * DKDIM * SEQ];
__device__ __half g_sc  [(size_t)BATCH * SEQ * SEQ];
__device__ __half g_ctx [(size_t)BATCH * SEQ * DKDIM];
__device__ __half g_wqkv[(size_t)3 * DKDIM * FDIM];          // [3*DK, F] = Wq^T|Wk^T|Wv^T
__device__ __half g_wot [(size_t)FDIM * DKDIM];
__device__ float  g_bqkv[(size_t)3 * DKDIM];

// ---------------------------------------------------------------------------
// Helpers
// ---------------------------------------------------------------------------
__device__ __forceinline__ uint32_t smem_u32(const void* p) {
    uint32_t a;
    asm("{ .reg .u64 t; cvta.to.shared.u64 t, %1; cvt.u32.u64 %0, t; }" : "=r"(a) : "l"(p));
    return a;
}
__device__ __forceinline__ void cp_async16(uint32_t dst, const void* src) {
    asm volatile("cp.async.cg.shared.global [%0], [%1], 16;" :: "r"(dst), "l"(src) : "memory");
}
__device__ __forceinline__ void cp_commit() {
    asm volatile("cp.async.commit_group;" ::: "memory");
}
__device__ __forceinline__ void cp_wait_1() {
    asm volatile("cp.async.wait_group 1;" ::: "memory");
}
__device__ __forceinline__ void ldmatrix_x4(uint32_t* r, uint32_t addr) {
    asm volatile("ldmatrix.sync.aligned.m8n8.x4.shared.b16 {%0,%1,%2,%3}, [%4];"
                 : "=r"(r[0]), "=r"(r[1]), "=r"(r[2]), "=r"(r[3]) : "r"(addr));
}
__device__ __forceinline__ void mma_f16(float* d, const uint32_t* a,
                                        uint32_t b0, uint32_t b1) {
    asm volatile(
        "mma.sync.aligned.m16n8k16.row.col.f32.f16.f16.f32 "
        "{%0,%1,%2,%3}, {%4,%5,%6,%7}, {%8,%9}, {%0,%1,%2,%3};"
        : "+f"(d[0]), "+f"(d[1]), "+f"(d[2]), "+f"(d[3])
        : "r"(a[0]), "r"(a[1]), "r"(a[2]), "r"(a[3]), "r"(b0), "r"(b1));
}

// ---------------------------------------------------------------------------
// fp16 tensor-core GEMM:  C = alpha * A * B^T + bias
//   A: [M,K] half, row stride lda (batched by sA)
//   B: [N,K] half, row stride ldb (batched by sB)
//   C: [M,N], row stride ldc; half if c_half else float (batched by sC)
// M % 128 == 0, N % 256 == 0, K % 64 == 0.
// ---------------------------------------------------------------------------
__global__ void __launch_bounds__(GEMM_THREADS, 1)
gemm_f16_kernel(const __half* __restrict__ A, const __half* __restrict__ B,
                const float* __restrict__ bias, void* __restrict__ Cv,
                int M, int N, int K, int lda, int ldb, int ldc,
                long long sA, long long sB, long long sC,
                float alpha, int c_half)
{
    extern __shared__ __half sm[];
    const int tid = threadIdx.x;
    const int wid = tid >> 5;
    const int lane = tid & 31;
    const int g   = lane >> 2;         // 0..7
    const int tig = lane & 3;          // 0..3
    const int mw = (wid & 1) * 64;     // warp m offset (2 rows of warps)
    const int nw = (wid >> 1) * 64;    // warp n offset (4 cols of warps)

    A += (long long)blockIdx.z * sA;
    B += (long long)blockIdx.z * sB;
    const int m0 = blockIdx.y * BM;
    const int n0 = blockIdx.x * BN;

    float acc[4][8][4];
#pragma unroll
    for (int mt = 0; mt < 4; mt++)
#pragma unroll
        for (int nt = 0; nt < 8; nt++)
#pragma unroll
            for (int r = 0; r < 4; r++) acc[mt][nt][r] = 0.0f;

    const uint32_t sm_base = smem_u32(sm);
    const int KT = K / BK;

    auto load_stage = [&](int p) {
        const uint32_t base = sm_base + (uint32_t)((p % STAGES) * STAGE_HALVES) * 2u;
        const uint32_t bbase = base + A_STAGE_HALVES * 2u;
        const int k0 = p * BK;
#pragma unroll
        for (int t = 0; t < 4; t++) {                // A: 1024 chunks of 16B
            int c = tid + t * GEMM_THREADS;
            int r = c >> 3, kc = c & 7;
            cp_async16(base + (uint32_t)(r * ROWH + kc * 8) * 2u,
                       A + (long long)(m0 + r) * lda + k0 + kc * 8);
        }
#pragma unroll
        for (int t = 0; t < 8; t++) {                // B: 2048 chunks of 16B
            int c = tid + t * GEMM_THREADS;
            int r = c >> 3, kc = c & 7;
            cp_async16(bbase + (uint32_t)(r * ROWH + kc * 8) * 2u,
                       B + (long long)(n0 + r) * ldb + k0 + kc * 8);
        }
    };

    load_stage(0); cp_commit();
    load_stage(1); cp_commit();

    // ldmatrix per-lane row/k selects
    const int row_a  = ((lane >> 3) & 1) * 8 + (lane & 7);
    const int kadd_a = ((lane >> 4) & 1) * 8;
    const int row_b  = ((lane >> 4) & 1) * 8 + (lane & 7);
    const int kadd_b = ((lane >> 3) & 1) * 8;

    uint32_t a[2][4][4], b[2][4][4];

    for (int kt = 0; kt < KT; kt++) {
        cp_wait_1();                     // stage kt resident
        __syncthreads();                 // all warps done with stage kt-1

        if (kt + 2 < KT) load_stage(kt + 2);
        cp_commit();

        const uint32_t sa  = sm_base + (uint32_t)((kt % STAGES) * STAGE_HALVES) * 2u;
        const uint32_t sbp = sa + A_STAGE_HALVES * 2u;

        // prefetch kk = 0 fragments
#pragma unroll
        for (int mt = 0; mt < 4; mt++)
            ldmatrix_x4(a[0][mt], sa + (uint32_t)((mw + mt * 16 + row_a) * ROWH + kadd_a) * 2u);
#pragma unroll
        for (int i = 0; i < 4; i++)
            ldmatrix_x4(b[0][i], sbp + (uint32_t)((nw + i * 16 + row_b) * ROWH + kadd_b) * 2u);

#pragma unroll
        for (int kk = 0; kk < 4; kk++) {
            const int cur = kk & 1, nxt = cur ^ 1;
            if (kk < 3) {
                const int k16 = (kk + 1) * 16;
#pragma unroll
                for (int mt = 0; mt < 4; mt++)
                    ldmatrix_x4(a[nxt][mt],
                        sa + (uint32_t)((mw + mt * 16 + row_a) * ROWH + k16 + kadd_a) * 2u);
#pragma unroll
                for (int i = 0; i < 4; i++)
                    ldmatrix_x4(b[nxt][i],
                        sbp + (uint32_t)((nw + i * 16 + row_b) * ROWH + k16 + kadd_b) * 2u);
            }
#pragma unroll
            for (int mt = 0; mt < 4; mt++)
#pragma unroll
                for (int nt = 0; nt < 8; nt++)
                    mma_f16(acc[mt][nt], a[cur][mt],
                            b[cur][nt >> 1][(nt & 1) * 2], b[cur][nt >> 1][(nt & 1) * 2 + 1]);
        }
    }

    // ---- epilogue ----
#pragma unroll
    for (int mt = 0; mt < 4; mt++) {
        const int m = m0 + mw + mt * 16 + g;
#pragma unroll
        for (int nt = 0; nt < 8; nt++) {
            const int n = n0 + nw + nt * 8 + 2 * tig;
            float2 v0, v1;
            v0.x = acc[mt][nt][0] * alpha;
            v0.y = acc[mt][nt][1] * alpha;
            v1.x = acc[mt][nt][2] * alpha;
            v1.y = acc[mt][nt][3] * alpha;
            if (bias) {
                float bx = bias[n], by = bias[n + 1];
                v0.x += bx; v0.y += by;
                v1.x += bx; v1.y += by;
            }
            if (c_half) {
                __half* C = (__half*)Cv + (long long)blockIdx.z * sC;
                *(__half2*)(C + (long long)m * ldc + n)       = __floats2half2_rn(v0.x, v0.y);
                *(__half2*)(C + (long long)(m + 8) * ldc + n) = __floats2half2_rn(v1.x, v1.y);
            } else {
                float* C = (float*)Cv + (long long)blockIdx.z * sC;
                *(float2*)(C + (long long)m * ldc + n)       = v0;
                *(float2*)(C + (long long)(m + 8) * ldc + n) = v1;
            }
        }
    }
}

// ---------------------------------------------------------------------------
// fp32 -> fp16 copy (for x)
// ---------------------------------------------------------------------------
__global__ void __launch_bounds__(256)
f2h_kernel(const float* __restrict__ in, __half* __restrict__ out)
{
    size_t i = (size_t)blockIdx.x * blockDim.x + threadIdx.x;
    float4 v = ((const float4*)in)[i];
    ((__half2*)out)[2 * i]     = __floats2half2_rn(v.x, v.y);
    ((__half2*)out)[2 * i + 1] = __floats2half2_rn(v.z, v.w);
}

// ---------------------------------------------------------------------------
// Batched QKV weight transpose fp32 [F,DK] -> half rows of [3*DK, F]
// z = 0/1/2 selects Wq/Wk/Wv; out offset z*DK*F.
// ---------------------------------------------------------------------------
__global__ void __launch_bounds__(256)
transpose_qkv_kernel(const float* __restrict__ wq, const float* __restrict__ wk,
                     const float* __restrict__ wv, __half* __restrict__ out)
{
    __shared__ float t[32][33];
    const float* in = (blockIdx.z == 0) ? wq : (blockIdx.z == 1) ? wk : wv;
    __half* o = out + (size_t)blockIdx.z * DKDIM * FDIM;
    const int c0 = blockIdx.x * 32, r0 = blockIdx.y * 32;
#pragma unroll
    for (int i = 0; i < 32; i += 8)
        t[threadIdx.y + i][threadIdx.x] =
            in[(long long)(r0 + threadIdx.y + i) * DKDIM + c0 + threadIdx.x];
    __syncthreads();
#pragma unroll
    for (int i = 0; i < 32; i += 8)
        o[(long long)(c0 + threadIdx.y + i) * FDIM + r0 + threadIdx.x] =
            __float2half_rn(t[threadIdx.x][threadIdx.y + i]);
}

// ---------------------------------------------------------------------------
// Single weight transpose fp32 [R,C] -> half [C,R]  (Wo)
// ---------------------------------------------------------------------------
__global__ void __launch_bounds__(256)
transpose_f2h_kernel(const float* __restrict__ in, __half* __restrict__ out,
                     int R, int C)
{
    __shared__ float t[32][33];
    const int c0 = blockIdx.x * 32, r0 = blockIdx.y * 32;
#pragma unroll
    for (int i = 0; i < 32; i += 8)
        t[threadIdx.y + i][threadIdx.x] =
            in[(long long)(r0 + threadIdx.y + i) * C + c0 + threadIdx.x];
    __syncthreads();
#pragma unroll
    for (int i = 0; i < 32; i += 8)
        out[(long long)(c0 + threadIdx.y + i) * R + r0 + threadIdx.x] =
            __float2half_rn(t[threadIdx.x][threadIdx.y + i]);
}

// ---------------------------------------------------------------------------
// Pack bq|bk|bv into one float[3*DK]
// ---------------------------------------------------------------------------
__global__ void __launch_bounds__(256)
bias_concat_kernel(const float* __restrict__ bq, const float* __restrict__ bk,
                   const float* __restrict__ bv, float* __restrict__ out)
{
    int i = blockIdx.x * blockDim.x + threadIdx.x;      // 0..3071
    const float* src = (i < DKDIM) ? bq : (i < 2 * DKDIM) ? bk : bv;
    out[i] = src[i & (DKDIM - 1)];
}

// ---------------------------------------------------------------------------
// Batched transpose half [R,C slice] -> half [C,R]  (V^T), input row stride ldIn
// ---------------------------------------------------------------------------
__global__ void __launch_bounds__(256)
transpose_h_kernel(const __half* __restrict__ in, __half* __restrict__ out,
                   int R, int C, int ldIn, long long sIn, long long sOut)
{
    __shared__ __half t[32][34];
    in  += (long long)blockIdx.z * sIn;
    out += (long long)blockIdx.z * sOut;
    const int c0 = blockIdx.x * 32, r0 = blockIdx.y * 32;
#pragma unroll
    for (int i = 0; i < 32; i += 8)
        t[threadIdx.y + i][threadIdx.x] =
            in[(long long)(r0 + threadIdx.y + i) * ldIn + c0 + threadIdx.x];
    __syncthreads();
#pragma unroll
    for (int i = 0; i < 32; i += 8)
        out[(long long)(c0 + threadIdx.y + i) * R + r0 + threadIdx.x] =
            t[threadIdx.x][threadIdx.y + i];
}

// ---------------------------------------------------------------------------
// Softmax over the QUERY axis (axis=-2), half in/out, fp32 math.
// ---------------------------------------------------------------------------
__global__ void __launch_bounds__(256)
softmax_over_q_kernel(__half* __restrict__ scores)
{
    __shared__ float red[8][32];
    const int b = blockIdx.y;
    const int lane = threadIdx.x & 31;
    const int seg  = threadIdx.x >> 5;
    const int k = blockIdx.x * 32 + lane;
    __half* p = scores + (long long)b * SEQ * SEQ + k;
    const int q0 = seg * (SEQ / 8);
    const int q1 = q0 + (SEQ / 8);

    float m = -INFINITY;
    for (int q = q0; q < q1; q++) m = fmaxf(m, __half2float(p[(long long)q * SEQ]));
    red[seg][lane] = m;
    __syncthreads();
    float mm = -INFINITY;
#pragma unroll
    for (int s = 0; s < 8; s++) mm = fmaxf(mm, red[s][lane]);
    __syncthreads();

    float sum = 0.0f;
    for (int q = q0; q < q1; q++) sum += expf(__half2float(p[(long long)q * SEQ]) - mm);
    red[seg][lane] = sum;
    __syncthreads();
    float tot = 0.0f;
#pragma unroll
    for (int s = 0; s < 8; s++) tot += red[s][lane];
    const float inv = 1.0f / tot;

    for (int q = q0; q < q1; q++) {
        float v = expf(__half2float(p[(long long)q * SEQ]) - mm) * inv;
        p[(long long)q * SEQ] = __float2half_rn(v);
    }
}

// ---------------------------------------------------------------------------
// Launcher
// ---------------------------------------------------------------------------
extern "C" void kernel_launch(void* const* d_in, const int* in_sizes, int n_in,
                              void* d_out, int out_size)
{
    const float* x  = (const float*)d_in[0];
    const float* Wq = (const float*)d_in[1];
    const float* bq = (const float*)d_in[2];
    const float* Wk = (const float*)d_in[3];
    const float* bk = (const float*)d_in[4];
    const float* Wv = (const float*)d_in[5];
    const float* bv = (const float*)d_in[6];
    const float* Wo = (const float*)d_in[7];
    const float* bo = (const float*)d_in[8];
    float* out = (float*)d_out;

    __half *xh, *qkv, *vt, *sc, *ctx, *wqkv, *wot;
    float* bqkv;
    cudaGetSymbolAddress((void**)&xh,   g_xh);
    cudaGetSymbolAddress((void**)&qkv,  g_qkv);
    cudaGetSymbolAddress((void**)&vt,   g_vt);
    cudaGetSymbolAddress((void**)&sc,   g_sc);
    cudaGetSymbolAddress((void**)&ctx,  g_ctx);
    cudaGetSymbolAddress((void**)&wqkv, g_wqkv);
    cudaGetSymbolAddress((void**)&wot,  g_wot);
    cudaGetSymbolAddress((void**)&bqkv, g_bqkv);

    cudaFuncSetAttribute(gemm_f16_kernel,
                         cudaFuncAttributeMaxDynamicSharedMemorySize, GEMM_SMEM);

    const int MS = BATCH * SEQ;                        // 8192
    const int N3 = 3 * DKDIM;                          // 3072
    const long long sQKV = (long long)SEQ * N3;        // batch stride inside qkv
    const long long sQK  = (long long)SEQ * DKDIM;
    const long long sSS  = (long long)SEQ * SEQ;
    const float inv_sqrt_dk = 1.0f / 32.0f;

    // 0) x -> half; weights -> transposed half; bias concat
    f2h_kernel<<<(BATCH * SEQ * FDIM / 4) / 256, 256>>>(x, xh);
    {
        dim3 blk(32, 8);
        transpose_qkv_kernel<<<dim3(DKDIM / 32, FDIM / 32, 3), blk>>>(Wq, Wk, Wv, wqkv);
        transpose_f2h_kernel<<<dim3(FDIM / 32, DKDIM / 32, 1), blk>>>(Wo, wot, DKDIM, FDIM);
        bias_concat_kernel<<<N3 / 256, 256>>>(bq, bk, bv, bqkv);
    }

    // 1) fused QKV projection: [8192,3072] = xh * Wqkv^T + bqkv (half out)
    {
        dim3 grd(N3 / BN, MS / BM, 1);
        gemm_f16_kernel<<<grd, GEMM_THREADS, GEMM_SMEM>>>(
            xh, wqkv, bqkv, qkv, MS, N3, FDIM, FDIM, FDIM, N3, 0, 0, 0, 1.0f, 1);
    }

    // 2) scores = Q K^T / sqrt(dk)   (batched; Q,K strided inside qkv)
    {
        dim3 grd(SEQ / BN, SEQ / BM, BATCH);
        gemm_f16_kernel<<<grd, GEMM_THREADS, GEMM_SMEM>>>(
            qkv + 0, qkv + DKDIM, nullptr, sc, SEQ, SEQ, DKDIM, N3, N3, SEQ,
            sQKV, sQKV, sSS, inv_sqrt_dk, 1);
    }

    // 3) softmax over query axis (half in/out)
    softmax_over_q_kernel<<<dim3(SEQ / 32, BATCH), 256>>>(sc);

    // 3b) V^T per batch (V strided inside qkv)
    {
        dim3 blk(32, 8);
        dim3 g(DKDIM / 32, SEQ / 32, BATCH);
        transpose_h_kernel<<<g, blk>>>(qkv + 2 * DKDIM, vt, SEQ, DKDIM, N3, sQKV, sQK);
    }

    // 4) ctx = attn * V   (batched; B = V^T [DK,S] K-major; half out)
    {
        dim3 grd(DKDIM / BN, SEQ / BM, BATCH);
        gemm_f16_kernel<<<grd, GEMM_THREADS, GEMM_SMEM>>>(
            sc, vt, nullptr, ctx, SEQ, DKDIM, SEQ, SEQ, SEQ, DKDIM,
            sSS, sQK, sQK, 1.0f, 1);
    }

    // 5) out = ctx * Wo + bo   (fp32 out)
    {
        dim3 grd(FDIM / BN, MS / BM, 1);
        gemm_f16_kernel<<<grd, GEMM_THREADS, GEMM_SMEM>>>(
            ctx, wot, bo, out, MS, FDIM, DKDIM, DKDIM, DKDIM, FDIM,
            0, 0, 0, 1.0f, 0);
    }
}

// round 8
// speedup vs baseline: 1.0473x; 1.0473x over previous
#include <cuda_runtime.h>
#include <cuda_fp16.h>
#include <cstdint>
#include <math.h>

// ---------------------------------------------------------------------------
// Problem constants
// ---------------------------------------------------------------------------
#define BATCH 4
#define SEQ   2048
#define FDIM  1024
#define DKDIM 1024

// ---------------------------------------------------------------------------
// fp16 mma.sync GEMM tiling: CTA 128x256, warp 64x64, BK=64, 3 stages
// ---------------------------------------------------------------------------
#define BM 128
#define BN 256
#define BK 64
#define STAGES 3
#define GEMM_THREADS 256

#define ROWH 72                                  // padded row length in halves (BK + 8)
#define A_STAGE_HALVES (BM * ROWH)               // 9216
#define B_STAGE_HALVES (BN * ROWH)               // 18432
#define STAGE_HALVES   (A_STAGE_HALVES + B_STAGE_HALVES)
#define GEMM_SMEM      (STAGES * STAGE_HALVES * 2)   // 165,888 B

#define VSCALE 64.0f

// ---------------------------------------------------------------------------
// Scratch (device globals — no dynamic allocation allowed)
// ---------------------------------------------------------------------------
__device__ __half g_xh  [(size_t)BATCH * SEQ * FDIM];
__device__ __half g_qkv [(size_t)BATCH * SEQ * 3 * DKDIM];   // Q|K|V interleaved in N
__device__ __half g_vt  [(size_t)BATCH * DKDIM * SEQ];
__device__ __half g_sc  [(size_t)BATCH * SEQ * SEQ];         // exp(scores), unnormalized
__device__ __half g_ctx [(size_t)BATCH * SEQ * DKDIM];
__device__ __half g_wqkv[(size_t)3 * DKDIM * FDIM];          // [3*DK, F]
__device__ __half g_wot [(size_t)FDIM * DKDIM];
__device__ float  g_bqkv[(size_t)3 * DKDIM];
__device__ float  g_part[(size_t)BATCH * (SEQ / BM) * SEQ];  // per-M-tile column partials
__device__ float  g_colsum[(size_t)BATCH * SEQ];

// ---------------------------------------------------------------------------
// Helpers
// ---------------------------------------------------------------------------
__device__ __forceinline__ uint32_t smem_u32(const void* p) {
    uint32_t a;
    asm("{ .reg .u64 t; cvta.to.shared.u64 t, %1; cvt.u32.u64 %0, t; }" : "=r"(a) : "l"(p));
    return a;
}
__device__ __forceinline__ void cp_async16(uint32_t dst, const void* src) {
    asm volatile("cp.async.cg.shared.global [%0], [%1], 16;" :: "r"(dst), "l"(src) : "memory");
}
__device__ __forceinline__ void cp_commit() {
    asm volatile("cp.async.commit_group;" ::: "memory");
}
__device__ __forceinline__ void cp_wait_1() {
    asm volatile("cp.async.wait_group 1;" ::: "memory");
}
__device__ __forceinline__ void ldmatrix_x4(uint32_t* r, uint32_t addr) {
    asm volatile("ldmatrix.sync.aligned.m8n8.x4.shared.b16 {%0,%1,%2,%3}, [%4];"
                 : "=r"(r[0]), "=r"(r[1]), "=r"(r[2]), "=r"(r[3]) : "r"(addr));
}
__device__ __forceinline__ void mma_f16(float* d, const uint32_t* a,
                                        uint32_t b0, uint32_t b1) {
    asm volatile(
        "mma.sync.aligned.m16n8k16.row.col.f32.f16.f16.f32 "
        "{%0,%1,%2,%3}, {%4,%5,%6,%7}, {%8,%9}, {%0,%1,%2,%3};"
        : "+f"(d[0]), "+f"(d[1]), "+f"(d[2]), "+f"(d[3])
        : "r"(a[0]), "r"(a[1]), "r"(a[2]), "r"(a[3]), "r"(b0), "r"(b1));
}

// ---------------------------------------------------------------------------
// fp16 tensor-core GEMM:  C = op(alpha * A * B^T + bias)
//   mode 0: plain (c_half selects half/float out)
//   mode 1: C = exp(alpha * acc) as half, plus per-CTA column sums -> part
// A: [M,K] half, stride lda (batch sA); B: [N,K] half, stride ldb (batch sB)
// C: [M,N] stride ldc (batch sC). M%128==0, N%256==0, K%64==0.
// ---------------------------------------------------------------------------
__global__ void __launch_bounds__(GEMM_THREADS, 1)
gemm_f16_kernel(const __half* __restrict__ A, const __half* __restrict__ B,
                const float* __restrict__ bias, void* __restrict__ Cv,
                float* __restrict__ part,
                int M, int N, int K, int lda, int ldb, int ldc,
                long long sA, long long sB, long long sC,
                float alpha, int c_half, int mode)
{
    extern __shared__ __half sm[];
    __shared__ float csum[2][BN];
    const int tid = threadIdx.x;
    const int wid = tid >> 5;
    const int lane = tid & 31;
    const int g   = lane >> 2;         // 0..7
    const int tig = lane & 3;          // 0..3
    const int mw = (wid & 1) * 64;     // warp m offset (2 rows of warps)
    const int nw = (wid >> 1) * 64;    // warp n offset (4 cols of warps)

    A += (long long)blockIdx.z * sA;
    B += (long long)blockIdx.z * sB;
    const int m0 = blockIdx.y * BM;
    const int n0 = blockIdx.x * BN;

    float acc[4][8][4];
#pragma unroll
    for (int mt = 0; mt < 4; mt++)
#pragma unroll
        for (int nt = 0; nt < 8; nt++)
#pragma unroll
            for (int r = 0; r < 4; r++) acc[mt][nt][r] = 0.0f;

    const uint32_t sm_base = smem_u32(sm);
    const int KT = K / BK;

    auto load_stage = [&](int p) {
        const uint32_t base = sm_base + (uint32_t)((p % STAGES) * STAGE_HALVES) * 2u;
        const uint32_t bbase = base + A_STAGE_HALVES * 2u;
        const int k0 = p * BK;
#pragma unroll
        for (int t = 0; t < 4; t++) {                // A: 1024 chunks of 16B
            int c = tid + t * GEMM_THREADS;
            int r = c >> 3, kc = c & 7;
            cp_async16(base + (uint32_t)(r * ROWH + kc * 8) * 2u,
                       A + (long long)(m0 + r) * lda + k0 + kc * 8);
        }
#pragma unroll
        for (int t = 0; t < 8; t++) {                // B: 2048 chunks of 16B
            int c = tid + t * GEMM_THREADS;
            int r = c >> 3, kc = c & 7;
            cp_async16(bbase + (uint32_t)(r * ROWH + kc * 8) * 2u,
                       B + (long long)(n0 + r) * ldb + k0 + kc * 8);
        }
    };

    load_stage(0); cp_commit();
    load_stage(1); cp_commit();

    const int row_a  = ((lane >> 3) & 1) * 8 + (lane & 7);
    const int kadd_a = ((lane >> 4) & 1) * 8;
    const int row_b  = ((lane >> 4) & 1) * 8 + (lane & 7);
    const int kadd_b = ((lane >> 3) & 1) * 8;

    uint32_t a[2][4][4], b[2][4][4];

    for (int kt = 0; kt < KT; kt++) {
        cp_wait_1();
        __syncthreads();

        if (kt + 2 < KT) load_stage(kt + 2);
        cp_commit();

        const uint32_t sa  = sm_base + (uint32_t)((kt % STAGES) * STAGE_HALVES) * 2u;
        const uint32_t sbp = sa + A_STAGE_HALVES * 2u;

#pragma unroll
        for (int mt = 0; mt < 4; mt++)
            ldmatrix_x4(a[0][mt], sa + (uint32_t)((mw + mt * 16 + row_a) * ROWH + kadd_a) * 2u);
#pragma unroll
        for (int i = 0; i < 4; i++)
            ldmatrix_x4(b[0][i], sbp + (uint32_t)((nw + i * 16 + row_b) * ROWH + kadd_b) * 2u);

#pragma unroll
        for (int kk = 0; kk < 4; kk++) {
            const int cur = kk & 1, nxt = cur ^ 1;
            if (kk < 3) {
                const int k16 = (kk + 1) * 16;
#pragma unroll
                for (int mt = 0; mt < 4; mt++)
                    ldmatrix_x4(a[nxt][mt],
                        sa + (uint32_t)((mw + mt * 16 + row_a) * ROWH + k16 + kadd_a) * 2u);
#pragma unroll
                for (int i = 0; i < 4; i++)
                    ldmatrix_x4(b[nxt][i],
                        sbp + (uint32_t)((nw + i * 16 + row_b) * ROWH + k16 + kadd_b) * 2u);
            }
#pragma unroll
            for (int mt = 0; mt < 4; mt++)
#pragma unroll
                for (int nt = 0; nt < 8; nt++)
                    mma_f16(acc[mt][nt], a[cur][mt],
                            b[cur][nt >> 1][(nt & 1) * 2], b[cur][nt >> 1][(nt & 1) * 2 + 1]);
        }
    }

    if (mode == 1) {
        // ---- exp epilogue + deterministic column partial sums ----
        __half* C = (__half*)Cv + (long long)blockIdx.z * sC;
        float cs0[8], cs1[8];
#pragma unroll
        for (int nt = 0; nt < 8; nt++) { cs0[nt] = 0.0f; cs1[nt] = 0.0f; }
#pragma unroll
        for (int mt = 0; mt < 4; mt++) {
            const int m = m0 + mw + mt * 16 + g;
#pragma unroll
            for (int nt = 0; nt < 8; nt++) {
                const int n = n0 + nw + nt * 8 + 2 * tig;
                float e0 = __expf(acc[mt][nt][0] * alpha);
                float e1 = __expf(acc[mt][nt][1] * alpha);
                float e2 = __expf(acc[mt][nt][2] * alpha);
                float e3 = __expf(acc[mt][nt][3] * alpha);
                cs0[nt] += e0 + e2;
                cs1[nt] += e1 + e3;
                *(__half2*)(C + (long long)m * ldc + n)       = __floats2half2_rn(e0, e1);
                *(__half2*)(C + (long long)(m + 8) * ldc + n) = __floats2half2_rn(e2, e3);
            }
        }
        // reduce over g (lane bits 2..4)
#pragma unroll
        for (int msk = 4; msk <= 16; msk <<= 1) {
#pragma unroll
            for (int nt = 0; nt < 8; nt++) {
                cs0[nt] += __shfl_xor_sync(0xffffffffu, cs0[nt], msk);
                cs1[nt] += __shfl_xor_sync(0xffffffffu, cs1[nt], msk);
            }
        }
        if (g == 0) {
#pragma unroll
            for (int nt = 0; nt < 8; nt++) {
                csum[wid & 1][nw + nt * 8 + 2 * tig]     = cs0[nt];
                csum[wid & 1][nw + nt * 8 + 2 * tig + 1] = cs1[nt];
            }
        }
        __syncthreads();
        // one partial row per (batch, M-tile)
        part[((long long)blockIdx.z * (SEQ / BM) + blockIdx.y) * SEQ + n0 + tid] =
            csum[0][tid] + csum[1][tid];
        return;
    }

    // ---- plain epilogue ----
#pragma unroll
    for (int mt = 0; mt < 4; mt++) {
        const int m = m0 + mw + mt * 16 + g;
#pragma unroll
        for (int nt = 0; nt < 8; nt++) {
            const int n = n0 + nw + nt * 8 + 2 * tig;
            float2 v0, v1;
            v0.x = acc[mt][nt][0] * alpha;
            v0.y = acc[mt][nt][1] * alpha;
            v1.x = acc[mt][nt][2] * alpha;
            v1.y = acc[mt][nt][3] * alpha;
            if (bias) {
                float bx = bias[n], by = bias[n + 1];
                v0.x += bx; v0.y += by;
                v1.x += bx; v1.y += by;
            }
            if (c_half) {
                __half* C = (__half*)Cv + (long long)blockIdx.z * sC;
                *(__half2*)(C + (long long)m * ldc + n)       = __floats2half2_rn(v0.x, v0.y);
                *(__half2*)(C + (long long)(m + 8) * ldc + n) = __floats2half2_rn(v1.x, v1.y);
            } else {
                float* C = (float*)Cv + (long long)blockIdx.z * sC;
                *(float2*)(C + (long long)m * ldc + n)       = v0;
                *(float2*)(C + (long long)(m + 8) * ldc + n) = v1;
            }
        }
    }
}

// ---------------------------------------------------------------------------
// colsum[b,n] = sum over 16 M-tiles of partials
// ---------------------------------------------------------------------------
__global__ void __launch_bounds__(256)
colsum_reduce_kernel(const float* __restrict__ part, float* __restrict__ colsum)
{
    const int i = blockIdx.x * 256 + threadIdx.x;       // 0..B*SEQ-1
    const int b = i >> 11, n = i & (SEQ - 1);
    float s = 0.0f;
#pragma unroll
    for (int t = 0; t < SEQ / BM; t++)
        s += part[((long long)b * (SEQ / BM) + t) * SEQ + n];
    colsum[i] = s;
}

// ---------------------------------------------------------------------------
// fp32 -> fp16 copy (for x)
// ---------------------------------------------------------------------------
__global__ void __launch_bounds__(256)
f2h_kernel(const float* __restrict__ in, __half* __restrict__ out)
{
    size_t i = (size_t)blockIdx.x * blockDim.x + threadIdx.x;
    float4 v = ((const float4*)in)[i];
    ((__half2*)out)[2 * i]     = __floats2half2_rn(v.x, v.y);
    ((__half2*)out)[2 * i + 1] = __floats2half2_rn(v.z, v.w);
}

// ---------------------------------------------------------------------------
// Batched QKV weight transpose fp32 [F,DK] -> half rows of [3*DK, F]
// ---------------------------------------------------------------------------
__global__ void __launch_bounds__(256)
transpose_qkv_kernel(const float* __restrict__ wq, const float* __restrict__ wk,
                     const float* __restrict__ wv, __half* __restrict__ out)
{
    __shared__ float t[32][33];
    const float* in = (blockIdx.z == 0) ? wq : (blockIdx.z == 1) ? wk : wv;
    __half* o = out + (size_t)blockIdx.z * DKDIM * FDIM;
    const int c0 = blockIdx.x * 32, r0 = blockIdx.y * 32;
#pragma unroll
    for (int i = 0; i < 32; i += 8)
        t[threadIdx.y + i][threadIdx.x] =
            in[(long long)(r0 + threadIdx.y + i) * DKDIM + c0 + threadIdx.x];
    __syncthreads();
#pragma unroll
    for (int i = 0; i < 32; i += 8)
        o[(long long)(c0 + threadIdx.y + i) * FDIM + r0 + threadIdx.x] =
            __float2half_rn(t[threadIdx.x][threadIdx.y + i]);
}

// ---------------------------------------------------------------------------
// Single weight transpose fp32 [R,C] -> half [C,R]  (Wo)
// ---------------------------------------------------------------------------
__global__ void __launch_bounds__(256)
transpose_f2h_kernel(const float* __restrict__ in, __half* __restrict__ out,
                     int R, int C)
{
    __shared__ float t[32][33];
    const int c0 = blockIdx.x * 32, r0 = blockIdx.y * 32;
#pragma unroll
    for (int i = 0; i < 32; i += 8)
        t[threadIdx.y + i][threadIdx.x] =
            in[(long long)(r0 + threadIdx.y + i) * C + c0 + threadIdx.x];
    __syncthreads();
#pragma unroll
    for (int i = 0; i < 32; i += 8)
        out[(long long)(c0 + threadIdx.y + i) * R + r0 + threadIdx.x] =
            __float2half_rn(t[threadIdx.x][threadIdx.y + i]);
}

// ---------------------------------------------------------------------------
// Pack bq|bk|bv into one float[3*DK]
// ---------------------------------------------------------------------------
__global__ void __launch_bounds__(256)
bias_concat_kernel(const float* __restrict__ bq, const float* __restrict__ bk,
                   const float* __restrict__ bv, float* __restrict__ out)
{
    int i = blockIdx.x * blockDim.x + threadIdx.x;
    const float* src = (i < DKDIM) ? bq : (i < 2 * DKDIM) ? bk : bv;
    out[i] = src[i & (DKDIM - 1)];
}

// ---------------------------------------------------------------------------
// V^T with softmax normalization folded in:
//   out[d, k] = V[k, d] * VSCALE / colsum[b, k]
// in: half [R,C slice] with row stride ldIn
// ---------------------------------------------------------------------------
__global__ void __launch_bounds__(256)
transpose_scale_kernel(const __half* __restrict__ in, __half* __restrict__ out,
                       const float* __restrict__ colsum,
                       int R, int C, int ldIn, long long sIn, long long sOut)
{
    __shared__ __half t[32][34];
    in  += (long long)blockIdx.z * sIn;
    out += (long long)blockIdx.z * sOut;
    const int c0 = blockIdx.x * 32, r0 = blockIdx.y * 32;
#pragma unroll
    for (int i = 0; i < 32; i += 8)
        t[threadIdx.y + i][threadIdx.x] =
            in[(long long)(r0 + threadIdx.y + i) * ldIn + c0 + threadIdx.x];
    __syncthreads();
    const float inv = VSCALE / colsum[(long long)blockIdx.z * SEQ + r0 + threadIdx.x];
#pragma unroll
    for (int i = 0; i < 32; i += 8)
        out[(long long)(c0 + threadIdx.y + i) * R + r0 + threadIdx.x] =
            __float2half_rn(__half2float(t[threadIdx.x][threadIdx.y + i]) * inv);
}

// ---------------------------------------------------------------------------
// Launcher
// ---------------------------------------------------------------------------
extern "C" void kernel_launch(void* const* d_in, const int* in_sizes, int n_in,
                              void* d_out, int out_size)
{
    const float* x  = (const float*)d_in[0];
    const float* Wq = (const float*)d_in[1];
    const float* bq = (const float*)d_in[2];
    const float* Wk = (const float*)d_in[3];
    const float* bk = (const float*)d_in[4];
    const float* Wv = (const float*)d_in[5];
    const float* bv = (const float*)d_in[6];
    const float* Wo = (const float*)d_in[7];
    const float* bo = (const float*)d_in[8];
    float* out = (float*)d_out;

    __half *xh, *qkv, *vt, *sc, *ctx, *wqkv, *wot;
    float *bqkv, *part, *colsum;
    cudaGetSymbolAddress((void**)&xh,     g_xh);
    cudaGetSymbolAddress((void**)&qkv,    g_qkv);
    cudaGetSymbolAddress((void**)&vt,     g_vt);
    cudaGetSymbolAddress((void**)&sc,     g_sc);
    cudaGetSymbolAddress((void**)&ctx,    g_ctx);
    cudaGetSymbolAddress((void**)&wqkv,   g_wqkv);
    cudaGetSymbolAddress((void**)&wot,    g_wot);
    cudaGetSymbolAddress((void**)&bqkv,   g_bqkv);
    cudaGetSymbolAddress((void**)&part,   g_part);
    cudaGetSymbolAddress((void**)&colsum, g_colsum);

    cudaFuncSetAttribute(gemm_f16_kernel,
                         cudaFuncAttributeMaxDynamicSharedMemorySize, GEMM_SMEM);

    const int MS = BATCH * SEQ;                        // 8192
    const int N3 = 3 * DKDIM;                          // 3072
    const long long sQKV = (long long)SEQ * N3;
    const long long sQK  = (long long)SEQ * DKDIM;
    const long long sSS  = (long long)SEQ * SEQ;
    const float inv_sqrt_dk = 1.0f / 32.0f;

    // 0) x -> half; weights -> transposed half; bias concat
    f2h_kernel<<<(BATCH * SEQ * FDIM / 4) / 256, 256>>>(x, xh);
    {
        dim3 blk(32, 8);
        transpose_qkv_kernel<<<dim3(DKDIM / 32, FDIM / 32, 3), blk>>>(Wq, Wk, Wv, wqkv);
        transpose_f2h_kernel<<<dim3(FDIM / 32, DKDIM / 32, 1), blk>>>(Wo, wot, DKDIM, FDIM);
        bias_concat_kernel<<<N3 / 256, 256>>>(bq, bk, bv, bqkv);
    }

    // 1) fused QKV projection: [8192,3072] = xh * Wqkv^T + bqkv (half out)
    {
        dim3 grd(N3 / BN, MS / BM, 1);
        gemm_f16_kernel<<<grd, GEMM_THREADS, GEMM_SMEM>>>(
            xh, wqkv, bqkv, qkv, nullptr, MS, N3, FDIM, FDIM, FDIM, N3,
            0, 0, 0, 1.0f, 1, 0);
    }

    // 2) sc = exp(Q K^T / sqrt(dk)), plus column partial sums (mode 1)
    {
        dim3 grd(SEQ / BN, SEQ / BM, BATCH);
        gemm_f16_kernel<<<grd, GEMM_THREADS, GEMM_SMEM>>>(
            qkv + 0, qkv + DKDIM, nullptr, sc, part, SEQ, SEQ, DKDIM, N3, N3, SEQ,
            sQKV, sQKV, sSS, inv_sqrt_dk, 1, 1);
    }

    // 3) colsum reduce (16 partials -> 1)
    colsum_reduce_kernel<<<(BATCH * SEQ) / 256, 256>>>(part, colsum);

    // 3b) V^T with 64/colsum folded in
    {
        dim3 blk(32, 8);
        dim3 g(DKDIM / 32, SEQ / 32, BATCH);
        transpose_scale_kernel<<<g, blk>>>(qkv + 2 * DKDIM, vt, colsum,
                                           SEQ, DKDIM, N3, sQKV, sQK);
    }

    // 4) ctx = (1/64) * exp * Vscaled   (batched, half out)
    {
        dim3 grd(DKDIM / BN, SEQ / BM, BATCH);
        gemm_f16_kernel<<<grd, GEMM_THREADS, GEMM_SMEM>>>(
            sc, vt, nullptr, ctx, nullptr, SEQ, DKDIM, SEQ, SEQ, SEQ, DKDIM,
            sSS, sQK, sQK, 1.0f / VSCALE, 1, 0);
    }

    // 5) out = ctx * Wo + bo   (fp32 out)
    {
        dim3 grd(FDIM / BN, MS / BM, 1);
        gemm_f16_kernel<<<grd, GEMM_THREADS, GEMM_SMEM>>>(
            ctx, wot, bo, out, nullptr, MS, FDIM, DKDIM, DKDIM, DKDIM, FDIM,
            0, 0, 0, 1.0f, 0, 0);
    }
}

// round 9
// speedup vs baseline: 1.1671x; 1.1143x over previous
#include <cuda_runtime.h>
#include <cuda_fp16.h>
#include <cstdint>
#include <math.h>

// ---------------------------------------------------------------------------
// Problem constants
// ---------------------------------------------------------------------------
#define BATCH 4
#define SEQ   2048
#define FDIM  1024
#define DKDIM 1024

// ---------------------------------------------------------------------------
// fp16 mma.sync GEMM tiling: CTA 128x128, warp 64x32, BK=64, 3 stages, 2 CTA/SM
// ---------------------------------------------------------------------------
#define BM 128
#define BN 128
#define BK 64
#define STAGES 3
#define GEMM_THREADS 256

#define ROWH 72                                  // padded row length in halves (BK + 8)
#define A_STAGE_HALVES (BM * ROWH)               // 9216
#define B_STAGE_HALVES (BN * ROWH)               // 9216
#define STAGE_HALVES   (A_STAGE_HALVES + B_STAGE_HALVES)
#define GEMM_SMEM      (STAGES * STAGE_HALVES * 2)   // 110,592 B

#define VSCALE 64.0f
#define MTILES (SEQ / BM)                        // 16 score M-tiles per batch

// ---------------------------------------------------------------------------
// Scratch (device globals — no dynamic allocation allowed)
// ---------------------------------------------------------------------------
__device__ __half g_xh  [(size_t)BATCH * SEQ * FDIM];
__device__ __half g_qkv [(size_t)BATCH * SEQ * 3 * DKDIM];   // Q|K|V interleaved in N
__device__ __half g_vt  [(size_t)BATCH * DKDIM * SEQ];
__device__ __half g_sc  [(size_t)BATCH * SEQ * SEQ];         // exp(scores), unnormalized
__device__ __half g_ctx [(size_t)BATCH * SEQ * DKDIM];
__device__ __half g_wqkv[(size_t)3 * DKDIM * FDIM];          // [3*DK, F]
__device__ __half g_wot [(size_t)FDIM * DKDIM];
__device__ float  g_bqkv[(size_t)3 * DKDIM];
__device__ float  g_part[(size_t)BATCH * MTILES * SEQ];      // per-M-tile column partials

// ---------------------------------------------------------------------------
// Helpers
// ---------------------------------------------------------------------------
__device__ __forceinline__ uint32_t smem_u32(const void* p) {
    uint32_t a;
    asm("{ .reg .u64 t; cvta.to.shared.u64 t, %1; cvt.u32.u64 %0, t; }" : "=r"(a) : "l"(p));
    return a;
}
__device__ __forceinline__ void cp_async16(uint32_t dst, const void* src) {
    asm volatile("cp.async.cg.shared.global [%0], [%1], 16;" :: "r"(dst), "l"(src) : "memory");
}
__device__ __forceinline__ void cp_commit() {
    asm volatile("cp.async.commit_group;" ::: "memory");
}
__device__ __forceinline__ void cp_wait_1() {
    asm volatile("cp.async.wait_group 1;" ::: "memory");
}
__device__ __forceinline__ void ldmatrix_x4(uint32_t* r, uint32_t addr) {
    asm volatile("ldmatrix.sync.aligned.m8n8.x4.shared.b16 {%0,%1,%2,%3}, [%4];"
                 : "=r"(r[0]), "=r"(r[1]), "=r"(r[2]), "=r"(r[3]) : "r"(addr));
}
__device__ __forceinline__ void mma_f16(float* d, const uint32_t* a,
                                        uint32_t b0, uint32_t b1) {
    asm volatile(
        "mma.sync.aligned.m16n8k16.row.col.f32.f16.f16.f32 "
        "{%0,%1,%2,%3}, {%4,%5,%6,%7}, {%8,%9}, {%0,%1,%2,%3};"
        : "+f"(d[0]), "+f"(d[1]), "+f"(d[2]), "+f"(d[3])
        : "r"(a[0]), "r"(a[1]), "r"(a[2]), "r"(a[3]), "r"(b0), "r"(b1));
}

// ---------------------------------------------------------------------------
// fp16 tensor-core GEMM:  C = op(alpha * A * B^T + bias)
//   mode 0: plain (c_half selects half/float out)
//   mode 1: C = exp(alpha * acc) as half, plus per-CTA column sums -> part
// A: [M,K] half, stride lda (batch sA); B: [N,K] half, stride ldb (batch sB)
// C: [M,N] stride ldc (batch sC). M%128==0, N%128==0, K%64==0.
// ---------------------------------------------------------------------------
__global__ void __launch_bounds__(GEMM_THREADS, 2)
gemm_f16_kernel(const __half* __restrict__ A, const __half* __restrict__ B,
                const float* __restrict__ bias, void* __restrict__ Cv,
                float* __restrict__ part,
                int M, int N, int K, int lda, int ldb, int ldc,
                long long sA, long long sB, long long sC,
                float alpha, int c_half, int mode)
{
    extern __shared__ __half sm[];
    __shared__ float csum[2][BN];
    const int tid = threadIdx.x;
    const int wid = tid >> 5;
    const int lane = tid & 31;
    const int g   = lane >> 2;         // 0..7
    const int tig = lane & 3;          // 0..3
    const int mw = (wid & 1) * 64;     // warp m offset (2 rows of warps)
    const int nw = (wid >> 1) * 32;    // warp n offset (4 cols of warps)

    A += (long long)blockIdx.z * sA;
    B += (long long)blockIdx.z * sB;
    const int m0 = blockIdx.y * BM;
    const int n0 = blockIdx.x * BN;

    float acc[4][4][4];
#pragma unroll
    for (int mt = 0; mt < 4; mt++)
#pragma unroll
        for (int nt = 0; nt < 4; nt++)
#pragma unroll
            for (int r = 0; r < 4; r++) acc[mt][nt][r] = 0.0f;

    const uint32_t sm_base = smem_u32(sm);
    const int KT = K / BK;

    auto load_stage = [&](int p) {
        const uint32_t base = sm_base + (uint32_t)((p % STAGES) * STAGE_HALVES) * 2u;
        const uint32_t bbase = base + A_STAGE_HALVES * 2u;
        const int k0 = p * BK;
#pragma unroll
        for (int t = 0; t < 4; t++) {                // A: 1024 chunks of 16B
            int c = tid + t * GEMM_THREADS;
            int r = c >> 3, kc = c & 7;
            cp_async16(base + (uint32_t)(r * ROWH + kc * 8) * 2u,
                       A + (long long)(m0 + r) * lda + k0 + kc * 8);
        }
#pragma unroll
        for (int t = 0; t < 4; t++) {                // B: 1024 chunks of 16B
            int c = tid + t * GEMM_THREADS;
            int r = c >> 3, kc = c & 7;
            cp_async16(bbase + (uint32_t)(r * ROWH + kc * 8) * 2u,
                       B + (long long)(n0 + r) * ldb + k0 + kc * 8);
        }
    };

    load_stage(0); cp_commit();
    load_stage(1); cp_commit();

    const int row_a  = ((lane >> 3) & 1) * 8 + (lane & 7);
    const int kadd_a = ((lane >> 4) & 1) * 8;
    const int row_b  = ((lane >> 4) & 1) * 8 + (lane & 7);
    const int kadd_b = ((lane >> 3) & 1) * 8;

    for (int kt = 0; kt < KT; kt++) {
        cp_wait_1();
        __syncthreads();

        if (kt + 2 < KT) load_stage(kt + 2);
        cp_commit();

        const uint32_t sa  = sm_base + (uint32_t)((kt % STAGES) * STAGE_HALVES) * 2u;
        const uint32_t sbp = sa + A_STAGE_HALVES * 2u;
#pragma unroll
        for (int kk = 0; kk < 4; kk++) {
            const int k16 = kk * 16;
            uint32_t a[4][4], b[2][4];
#pragma unroll
            for (int mt = 0; mt < 4; mt++)
                ldmatrix_x4(a[mt],
                    sa + (uint32_t)((mw + mt * 16 + row_a) * ROWH + k16 + kadd_a) * 2u);
#pragma unroll
            for (int i = 0; i < 2; i++)
                ldmatrix_x4(b[i],
                    sbp + (uint32_t)((nw + i * 16 + row_b) * ROWH + k16 + kadd_b) * 2u);
#pragma unroll
            for (int mt = 0; mt < 4; mt++)
#pragma unroll
                for (int nt = 0; nt < 4; nt++)
                    mma_f16(acc[mt][nt], a[mt],
                            b[nt >> 1][(nt & 1) * 2], b[nt >> 1][(nt & 1) * 2 + 1]);
        }
    }

    if (mode == 1) {
        // ---- exp epilogue + deterministic column partial sums ----
        __half* C = (__half*)Cv + (long long)blockIdx.z * sC;
        float cs0[4], cs1[4];
#pragma unroll
        for (int nt = 0; nt < 4; nt++) { cs0[nt] = 0.0f; cs1[nt] = 0.0f; }
#pragma unroll
        for (int mt = 0; mt < 4; mt++) {
            const int m = m0 + mw + mt * 16 + g;
#pragma unroll
            for (int nt = 0; nt < 4; nt++) {
                const int n = n0 + nw + nt * 8 + 2 * tig;
                float e0 = __expf(acc[mt][nt][0] * alpha);
                float e1 = __expf(acc[mt][nt][1] * alpha);
                float e2 = __expf(acc[mt][nt][2] * alpha);
                float e3 = __expf(acc[mt][nt][3] * alpha);
                cs0[nt] += e0 + e2;
                cs1[nt] += e1 + e3;
                *(__half2*)(C + (long long)m * ldc + n)       = __floats2half2_rn(e0, e1);
                *(__half2*)(C + (long long)(m + 8) * ldc + n) = __floats2half2_rn(e2, e3);
            }
        }
#pragma unroll
        for (int msk = 4; msk <= 16; msk <<= 1) {
#pragma unroll
            for (int nt = 0; nt < 4; nt++) {
                cs0[nt] += __shfl_xor_sync(0xffffffffu, cs0[nt], msk);
                cs1[nt] += __shfl_xor_sync(0xffffffffu, cs1[nt], msk);
            }
        }
        if (g == 0) {
#pragma unroll
            for (int nt = 0; nt < 4; nt++) {
                csum[wid & 1][nw + nt * 8 + 2 * tig]     = cs0[nt];
                csum[wid & 1][nw + nt * 8 + 2 * tig + 1] = cs1[nt];
            }
        }
        __syncthreads();
        if (tid < BN)
            part[((long long)blockIdx.z * MTILES + blockIdx.y) * SEQ + n0 + tid] =
                csum[0][tid] + csum[1][tid];
        return;
    }

    // ---- plain epilogue ----
#pragma unroll
    for (int mt = 0; mt < 4; mt++) {
        const int m = m0 + mw + mt * 16 + g;
#pragma unroll
        for (int nt = 0; nt < 4; nt++) {
            const int n = n0 + nw + nt * 8 + 2 * tig;
            float2 v0, v1;
            v0.x = acc[mt][nt][0] * alpha;
            v0.y = acc[mt][nt][1] * alpha;
            v1.x = acc[mt][nt][2] * alpha;
            v1.y = acc[mt][nt][3] * alpha;
            if (bias) {
                float bx = bias[n], by = bias[n + 1];
                v0.x += bx; v0.y += by;
                v1.x += bx; v1.y += by;
            }
            if (c_half) {
                __half* C = (__half*)Cv + (long long)blockIdx.z * sC;
                *(__half2*)(C + (long long)m * ldc + n)       = __floats2half2_rn(v0.x, v0.y);
                *(__half2*)(C + (long long)(m + 8) * ldc + n) = __floats2half2_rn(v1.x, v1.y);
            } else {
                float* C = (float*)Cv + (long long)blockIdx.z * sC;
                *(float2*)(C + (long long)m * ldc + n)       = v0;
                *(float2*)(C + (long long)(m + 8) * ldc + n) = v1;
            }
        }
    }
}

// ---------------------------------------------------------------------------
// Fused prep: x->half | Wq/Wk/Wv transpose->wqkv | Wo transpose->wot | bias
// 1D grid dispatch: [0,8192) f2h, [8192,11264) qkv-T, [11264,12288) Wo-T,
// [12288,12300) bias concat.
// ---------------------------------------------------------------------------
__global__ void __launch_bounds__(256)
prep_kernel(const float* __restrict__ x,
            const float* __restrict__ Wq, const float* __restrict__ Wk,
            const float* __restrict__ Wv, const float* __restrict__ Wo,
            const float* __restrict__ bq, const float* __restrict__ bk,
            const float* __restrict__ bv,
            __half* __restrict__ xh, __half* __restrict__ wqkv,
            __half* __restrict__ wot, float* __restrict__ bqkv)
{
    __shared__ float t[32][33];
    const int b = blockIdx.x;
    const int tid = threadIdx.x;
    const int tx = tid & 31, ty = tid >> 5;      // 32 x 8

    if (b < 8192) {
        // f2h on x
        size_t i = (size_t)b * 256 + tid;
        float4 v = ((const float4*)x)[i];
        ((__half2*)xh)[2 * i]     = __floats2half2_rn(v.x, v.y);
        ((__half2*)xh)[2 * i + 1] = __floats2half2_rn(v.z, v.w);
    } else if (b < 11264) {
        // QKV weight transpose [F,DK] -> [DK,F] slice z
        const int tt = b - 8192;
        const int z = tt >> 10;
        const int by = (tt & 1023) >> 5;   // row block over F
        const int bx = tt & 31;            // col block over DK
        const float* in = (z == 0) ? Wq : (z == 1) ? Wk : Wv;
        __half* o = wqkv + (size_t)z * DKDIM * FDIM;
        const int c0 = bx * 32, r0 = by * 32;
#pragma unroll
        for (int i = 0; i < 32; i += 8)
            t[ty + i][tx] = in[(long long)(r0 + ty + i) * DKDIM + c0 + tx];
        __syncthreads();
#pragma unroll
        for (int i = 0; i < 32; i += 8)
            o[(long long)(c0 + ty + i) * FDIM + r0 + tx] =
                __float2half_rn(t[tx][ty + i]);
    } else if (b < 12288) {
        // Wo transpose [DK,F] -> [F,DK]
        const int tt = b - 11264;
        const int by = tt >> 5;            // row block over DK
        const int bx = tt & 31;            // col block over F
        const int c0 = bx * 32, r0 = by * 32;
#pragma unroll
        for (int i = 0; i < 32; i += 8)
            t[ty + i][tx] = Wo[(long long)(r0 + ty + i) * FDIM + c0 + tx];
        __syncthreads();
#pragma unroll
        for (int i = 0; i < 32; i += 8)
            wot[(long long)(c0 + ty + i) * DKDIM + r0 + tx] =
                __float2half_rn(t[tx][ty + i]);
    } else {
        // bias concat
        const int i = (b - 12288) * 256 + tid;    // 0..3071
        const float* src = (i < DKDIM) ? bq : (i < 2 * DKDIM) ? bk : bv;
        bqkv[i] = src[i & (DKDIM - 1)];
    }
}

// ---------------------------------------------------------------------------
// V^T with softmax normalization folded in (colsum reduced inline from part):
//   out[d, k] = V[k, d] * VSCALE / sum_t part[b][t][k]
// ---------------------------------------------------------------------------
__global__ void __launch_bounds__(256)
transpose_scale_kernel(const __half* __restrict__ in, __half* __restrict__ out,
                       const float* __restrict__ part,
                       int R, int C, int ldIn, long long sIn, long long sOut)
{
    __shared__ __half t[32][34];
    in  += (long long)blockIdx.z * sIn;
    out += (long long)blockIdx.z * sOut;
    const int c0 = blockIdx.x * 32, r0 = blockIdx.y * 32;
#pragma unroll
    for (int i = 0; i < 32; i += 8)
        t[threadIdx.y + i][threadIdx.x] =
            in[(long long)(r0 + threadIdx.y + i) * ldIn + c0 + threadIdx.x];
    __syncthreads();
    // colsum for this thread's k = r0 + threadIdx.x
    const float* pp = part + (long long)blockIdx.z * MTILES * SEQ + r0 + threadIdx.x;
    float s = 0.0f;
#pragma unroll
    for (int tt = 0; tt < MTILES; tt++) s += pp[(long long)tt * SEQ];
    const float inv = VSCALE / s;
#pragma unroll
    for (int i = 0; i < 32; i += 8)
        out[(long long)(c0 + threadIdx.y + i) * R + r0 + threadIdx.x] =
            __float2half_rn(__half2float(t[threadIdx.x][threadIdx.y + i]) * inv);
}

// ---------------------------------------------------------------------------
// Launcher
// ---------------------------------------------------------------------------
extern "C" void kernel_launch(void* const* d_in, const int* in_sizes, int n_in,
                              void* d_out, int out_size)
{
    const float* x  = (const float*)d_in[0];
    const float* Wq = (const float*)d_in[1];
    const float* bq = (const float*)d_in[2];
    const float* Wk = (const float*)d_in[3];
    const float* bk = (const float*)d_in[4];
    const float* Wv = (const float*)d_in[5];
    const float* bv = (const float*)d_in[6];
    const float* Wo = (const float*)d_in[7];
    const float* bo = (const float*)d_in[8];
    float* out = (float*)d_out;

    __half *xh, *qkv, *vt, *sc, *ctx, *wqkv, *wot;
    float *bqkv, *part;
    cudaGetSymbolAddress((void**)&xh,   g_xh);
    cudaGetSymbolAddress((void**)&qkv,  g_qkv);
    cudaGetSymbolAddress((void**)&vt,   g_vt);
    cudaGetSymbolAddress((void**)&sc,   g_sc);
    cudaGetSymbolAddress((void**)&ctx,  g_ctx);
    cudaGetSymbolAddress((void**)&wqkv, g_wqkv);
    cudaGetSymbolAddress((void**)&wot,  g_wot);
    cudaGetSymbolAddress((void**)&bqkv, g_bqkv);
    cudaGetSymbolAddress((void**)&part, g_part);

    cudaFuncSetAttribute(gemm_f16_kernel,
                         cudaFuncAttributeMaxDynamicSharedMemorySize, GEMM_SMEM);

    const int MS = BATCH * SEQ;                        // 8192
    const int N3 = 3 * DKDIM;                          // 3072
    const long long sQKV = (long long)SEQ * N3;
    const long long sQK  = (long long)SEQ * DKDIM;
    const long long sSS  = (long long)SEQ * SEQ;
    const float inv_sqrt_dk = 1.0f / 32.0f;

    // 0) fused prep
    prep_kernel<<<12300, 256>>>(x, Wq, Wk, Wv, Wo, bq, bk, bv, xh, wqkv, wot, bqkv);

    // 1) fused QKV projection: [8192,3072] = xh * Wqkv^T + bqkv (half out)
    {
        dim3 grd(N3 / BN, MS / BM, 1);
        gemm_f16_kernel<<<grd, GEMM_THREADS, GEMM_SMEM>>>(
            xh, wqkv, bqkv, qkv, nullptr, MS, N3, FDIM, FDIM, FDIM, N3,
            0, 0, 0, 1.0f, 1, 0);
    }

    // 2) sc = exp(Q K^T / sqrt(dk)), plus column partial sums (mode 1)
    {
        dim3 grd(SEQ / BN, SEQ / BM, BATCH);
        gemm_f16_kernel<<<grd, GEMM_THREADS, GEMM_SMEM>>>(
            qkv + 0, qkv + DKDIM, nullptr, sc, part, SEQ, SEQ, DKDIM, N3, N3, SEQ,
            sQKV, sQKV, sSS, inv_sqrt_dk, 1, 1);
    }

    // 3) V^T with VSCALE/colsum folded in (colsum reduced inline)
    {
        dim3 blk(32, 8);
        dim3 g(DKDIM / 32, SEQ / 32, BATCH);
        transpose_scale_kernel<<<g, blk>>>(qkv + 2 * DKDIM, vt, part,
                                           SEQ, DKDIM, N3, sQKV, sQK);
    }

    // 4) ctx = (1/VSCALE) * exp * Vscaled   (batched, half out)
    {
        dim3 grd(DKDIM / BN, SEQ / BM, BATCH);
        gemm_f16_kernel<<<grd, GEMM_THREADS, GEMM_SMEM>>>(
            sc, vt, nullptr, ctx, nullptr, SEQ, DKDIM, SEQ, SEQ, SEQ, DKDIM,
            sSS, sQK, sQK, 1.0f / VSCALE, 1, 0);
    }

    // 5) out = ctx * Wo + bo   (fp32 out)
    {
        dim3 grd(FDIM / BN, MS / BM, 1);
        gemm_f16_kernel<<<grd, GEMM_THREADS, GEMM_SMEM>>>(
            ctx, wot, bo, out, nullptr, MS, FDIM, DKDIM, DKDIM, DKDIM, FDIM,
            0, 0, 0, 1.0f, 0, 0);
    }
}